// round 10
// baseline (speedup 1.0000x reference)
#include <cuda_runtime.h>
#include <math_constants.h>

// RandomFeatures, round 10: batch-pair f32x2 FMA (LDS.64 = free pack) +
// half-warp m-split. lane -> (pair=lane&15 -> batches 2p,2p+1; half=lane>>4 ->
// half of each m-range). xs pitch 34 floats: LDS.64 aligned + bank-perfect.
// Dynamic quarter-units via atomic; fence-free combine via acq_rel + L2 scratch.

#define MAX_KLEN 11
#define WARPS_PER_CTA 12
#define XPITCH 34            // floats per row (even -> 8B aligned pairs)
#define XP2    17            // ull (float2) per row
#define HALO 128
#define NQ 4
#define BGMAX 4
#define KMAX 8192
typedef unsigned long long ull;

__device__ int   g_ctr[BGMAX];                   // work counter (self-reset)
__device__ int   g_done[BGMAX];                  // CTA done counter (self-reset)
__device__ int   g_arr[BGMAX * KMAX];            // per-k quarter arrivals (self-reset)
__device__ float g_scr[(size_t)BGMAX * KMAX * NQ * 64];

#define PACK2(dst, lo, hi) \
    asm("mov.b64 %0, {%1, %2};" : "=l"(dst) : "f"(lo), "f"(hi))
#define UNPACK2(lo, hi, src) \
    asm("mov.b64 {%0, %1}, %2;" : "=f"(lo), "=f"(hi) : "l"(src))
#define FMA2(acc, a, b) \
    asm("fma.rn.f32x2 %0, %1, %2, %0;" : "+l"(acc) : "l"(a), "l"(b))

__device__ __forceinline__ int atom_add_acq_rel(int* ptr, int v) {
    int old;
    asm volatile("atom.global.add.acq_rel.gpu.s32 %0, [%1], %2;"
                 : "=r"(old) : "l"(ptr), "r"(v) : "memory");
    return old;
}

// One block: NB outputs (m-positions) x 2 batches per lane.
template<int KLEN, int NB>
__device__ __forceinline__ void blk(
    const ull* __restrict__ p, int dp2,
    const ull* __restrict__ W2, ull bs2,
    float& mx0, float& mx1, int& ic0, int& ic1)
{
    ull P[NB + KLEN - 1];
#pragma unroll
    for (int t = 0; t < NB + KLEN - 1; t++) P[t] = p[t * dp2];
#pragma unroll
    for (int i = 0; i < NB; i++) {
        ull A = bs2;
#pragma unroll
        for (int j = 0; j < KLEN; j++) FMA2(A, W2[j], P[i + j]);
        float a0, a1;
        UNPACK2(a0, a1, A);
        mx0 = fmaxf(mx0, a0); ic0 += (a0 > 0.0f) ? 1 : 0;
        mx1 = fmaxf(mx1, a1); ic1 += (a1 > 0.0f) ? 1 : 0;
    }
}

template<int KLEN>
__device__ __forceinline__ void conv_range(
    const ull* __restrict__ xsp,     // xs2 + pair
    int r, int pd, int mlo, int mhi, int d, int dp2,
    const ull* __restrict__ W2, ull bs2,
    float& mx0, float& mx1, int& ic0, int& ic1)
{
    int n = mhi - mlo;
    if (n <= 0) return;
    const ull* p = xsp + (HALO + r - pd + mlo * d) * XP2;
    while (n >= 8) { blk<KLEN, 8>(p, dp2, W2, bs2, mx0, mx1, ic0, ic1); p += 8 * dp2; n -= 8; }
    if (n & 4) { blk<KLEN, 4>(p, dp2, W2, bs2, mx0, mx1, ic0, ic1); p += 4 * dp2; }
    if (n & 2) { blk<KLEN, 2>(p, dp2, W2, bs2, mx0, mx1, ic0, ic1); p += 2 * dp2; }
    if (n & 1) { blk<KLEN, 1>(p, dp2, W2, bs2, mx0, mx1, ic0, ic1); }
}

template<int KLEN>
__device__ __forceinline__ void process_unit(
    const ull* __restrict__ xsp, int d, int pd, int ol, int q, int half,
    const ull* __restrict__ W2, ull bs2,
    float& mx0, float& mx1, int& ic0, int& ic1)
{
    const int dp2 = d * XP2;
    const int q0 = (ol - 1) / d;                 // one division per unit
    const int rr = (ol - 1) - q0 * d;
    if (d >= NQ) {
        for (int r = q; r < d; r += NQ) {
            const int M = (r <= rr) ? q0 + 1 : q0;   // ceil((ol-r)/d)
            const int mh = (M + 1) >> 1;
            conv_range<KLEN>(xsp, r, pd, half ? mh : 0, half ? M : mh,
                             d, dp2, W2, bs2, mx0, mx1, ic0, ic1);
        }
    } else {
        const int e = q * 2 + half;              // eighth split
        for (int r = 0; r < d; r++) {
            const int M = (r <= rr) ? q0 + 1 : q0;
            conv_range<KLEN>(xsp, r, pd, (e * M) >> 3, ((e + 1) * M) >> 3,
                             d, dp2, W2, bs2, mx0, mx1, ic0, ic1);
        }
    }
}

// Cold safe fallback for parameters outside the halo guarantee.
template<int KLEN>
__device__ __forceinline__ void process_unit_safe(
    const float* __restrict__ xs, int pair, int d, int pd, int ol, int q,
    int half, int T, const float* __restrict__ w, float bs,
    float& mx0, float& mx1, int& ic0, int& ic1)
{
    const int e = q * 2 + half;
    const int lo = (e * ol) >> 3, hi = ((e + 1) * ol) >> 3;
    for (int p = lo; p < hi; p++) {
        float a0 = bs, a1 = bs;
#pragma unroll
        for (int j = 0; j < KLEN; j++) {
            const long long ix = (long long)p - pd + (long long)j * d;
            const int ixc = (int)min(max(ix, 0LL), (long long)(T - 1));
            const bool ok = (ix >= 0 && ix < T);
            float v0 = xs[(HALO + ixc) * XPITCH + 2 * pair];
            float v1 = xs[(HALO + ixc) * XPITCH + 2 * pair + 1];
            a0 = fmaf(w[j], ok ? v0 : 0.0f, a0);
            a1 = fmaf(w[j], ok ? v1 : 0.0f, a1);
        }
        mx0 = fmaxf(mx0, a0); ic0 += (a0 > 0.0f) ? 1 : 0;
        mx1 = fmaxf(mx1, a1); ic1 += (a1 > 0.0f) ? 1 : 0;
    }
}

__global__ void __launch_bounds__(32 * WARPS_PER_CTA, 2)
rf_main(const float* __restrict__ x,
        const float* __restrict__ w,
        const float* __restrict__ bias,
        const int*   __restrict__ dil,
        const int*   __restrict__ padr,
        const int*   __restrict__ olen,
        float* __restrict__ out,
        int B, int T, int K)
{
    extern __shared__ float xs[];                 // [(2*HALO+T)][XPITCH]
    const int lane = threadIdx.x & 31;
    const int warp = threadIdx.x >> 5;
    const int pair = lane & 15;
    const int half = lane >> 4;
    const int bg   = blockIdx.y;
    const int b0   = bg * 32;
    const int nb   = min(32, B - b0);

    // Transposed fill with zero halos (2-way STS conflicts; tiny).
    for (int bb = warp; bb < 32; bb += WARPS_PER_CTA) {
        const int bsafe = min(bb, nb - 1);
        for (int t = lane; t < HALO; t += 32) {
            xs[t * XPITCH + bb] = 0.0f;
            xs[(HALO + T + t) * XPITCH + bb] = 0.0f;
        }
        for (int t = lane; t < T; t += 32) {
            float v = x[(size_t)(b0 + bsafe) * T + t];
            xs[(HALO + t) * XPITCH + bb] = (bb < nb) ? v : 0.0f;
        }
    }
    __syncthreads();

    const ull* xsp = (const ull*)xs + pair;       // batch-pair base
    const int nunits = K * NQ;

    for (;;) {
        int u = 0;
        if (lane == 0) u = atomicAdd(&g_ctr[bg], 1);
        u = __shfl_sync(0xFFFFFFFFu, u, 0);
        if (u >= nunits) break;

        const int k = u >> 2;
        const int q = u & (NQ - 1);
        const int   d  = dil[k];
        const int   pd = padr[k];
        const int   ol = olen[k];
        const float bv = bias[k];

        float wreg[MAX_KLEN];
#pragma unroll
        for (int j = 0; j < MAX_KLEN; j++)
            wreg[j] = __ldg(&w[(size_t)k * MAX_KLEN + j]);
        ull W2[MAX_KLEN];
#pragma unroll
        for (int j = 0; j < MAX_KLEN; j++) PACK2(W2[j], wreg[j], wreg[j]);
        ull bs2; PACK2(bs2, bv, bv);

        float mx0 = -CUDART_INF_F, mx1 = -CUDART_INF_F;
        int   ic0 = 0, ic1 = 0;

        // klen inference: taps >= klen are exactly zero by construction.
        const int klen = (wreg[9] != 0.0f || wreg[10] != 0.0f) ? 11
                       : (wreg[7] != 0.0f || wreg[8] != 0.0f) ? 9 : 7;
        const bool safe = (d >= 1) && (pd < HALO) &&
                          ((ol - 1) - pd + (long long)(klen - 1) * d < T + HALO);

        if (safe) {
            if (klen == 11)      process_unit<11>(xsp, d, pd, ol, q, half, W2, bs2, mx0, mx1, ic0, ic1);
            else if (klen == 9)  process_unit<9>(xsp, d, pd, ol, q, half, W2, bs2, mx0, mx1, ic0, ic1);
            else                 process_unit<7>(xsp, d, pd, ol, q, half, W2, bs2, mx0, mx1, ic0, ic1);
        } else if (d >= 1) {
            if (klen == 11)      process_unit_safe<11>(xs, pair, d, pd, ol, q, half, T, wreg, bv, mx0, mx1, ic0, ic1);
            else if (klen == 9)  process_unit_safe<9>(xs, pair, d, pd, ol, q, half, T, wreg, bv, mx0, mx1, ic0, ic1);
            else                 process_unit_safe<7>(xs, pair, d, pd, ol, q, half, T, wreg, bv, mx0, mx1, ic0, ic1);
        }

        // Merge the two halves (same batch pair lives in lanes p and p+16).
        mx0 = fmaxf(mx0, __shfl_xor_sync(0xFFFFFFFFu, mx0, 16));
        mx1 = fmaxf(mx1, __shfl_xor_sync(0xFFFFFFFFu, mx1, 16));
        ic0 += __shfl_xor_sync(0xFFFFFFFFu, ic0, 16);
        ic1 += __shfl_xor_sync(0xFFFFFFFFu, ic1, 16);

        // Publish partial via L2 (no L1 copies -> no fences needed).
        float* s = g_scr + (((size_t)bg * KMAX + k) * NQ + q) * 64;
        if (half == 0) {
            __stcg((float2*)&s[2 * pair], make_float2(mx0, mx1));
            __stcg((float2*)&s[32 + 2 * pair], make_float2((float)ic0, (float)ic1));
        }
        int arrived = 0;
        if (lane == 0) arrived = atom_add_acq_rel(&g_arr[bg * KMAX + k], 1);
        arrived = __shfl_sync(0xFFFFFFFFu, arrived, 0);
        if (arrived == NQ - 1) {
            const float* sb = g_scr + (((size_t)bg * KMAX + k) * NQ) * 64;
            float M = __ldcg(&sb[lane]), C = __ldcg(&sb[32 + lane]);
#pragma unroll
            for (int q2 = 1; q2 < NQ; q2++) {
                M  = fmaxf(M, __ldcg(&sb[q2 * 64 + lane]));
                C += __ldcg(&sb[q2 * 64 + 32 + lane]);
            }
            if (lane < nb) {
                float* o = out + (size_t)(b0 + lane) * 2 * K + 2 * k;
                o[0] = M;
                o[1] = C / (float)ol;
            }
            if (lane == 0) g_arr[bg * KMAX + k] = 0;   // self-reset for replay
        }
    }

    // Last CTA per batch group resets the work counter for the next replay.
    __syncthreads();
    if (threadIdx.x == 0) {
        int dn = atomicAdd(&g_done[bg], 1);
        if (dn == (int)gridDim.x - 1) {
            g_ctr[bg]  = 0;
            g_done[bg] = 0;
        }
    }
}

extern "C" void kernel_launch(void* const* d_in, const int* in_sizes, int n_in,
                              void* d_out, int out_size) {
    const float* x    = (const float*)d_in[0];
    const float* w    = (const float*)d_in[1];
    const float* bias = (const float*)d_in[2];
    const int*   dil  = (const int*)d_in[3];
    const int*   padr = (const int*)d_in[4];
    const int*   olen = (const int*)d_in[5];
    float* out = (float*)d_out;

    const int K = in_sizes[2];                 // bias element count
    const int B = out_size / (2 * K);
    const int T = in_sizes[0] / B;
    const int nbg = (B + 31) / 32;             // batch groups (<= BGMAX)

    const size_t smem = (size_t)(2 * HALO + T) * XPITCH * sizeof(float);
    cudaFuncSetAttribute(rf_main,
                         cudaFuncAttributeMaxDynamicSharedMemorySize,
                         (int)smem);

    // 2 CTAs/SM x 148 SMs persistent, split across batch groups.
    int ctas_per_bg = (296 + nbg - 1) / nbg;
    dim3 grid(ctas_per_bg, nbg);
    rf_main<<<grid, 32 * WARPS_PER_CTA, smem>>>(x, w, bias, dil, padr, olen,
                                                out, B, T, K);
}

// round 11
// speedup vs baseline: 1.0360x; 1.0360x over previous
#include <cuda_runtime.h>
#include <math_constants.h>

// RandomFeatures, round 11: r9 scalar carry-window core + NQ=8 eighth-units
// (halves scheduling tail) + software-pipelined unit fetch (atomic latency
// hidden behind current unit's compute).
// lane = batch; xs transposed [(HALO+T+HALO)][33] in shared; warp-uniform row
// index => conflict-free. Fence-free combine via acq_rel atomic + L2 scratch.

#define MAX_KLEN 11
#define WARPS_PER_CTA 15
#define XPITCH 33
#define HALO 128
#define NQ 8
#define NQ_SHIFT 3
#define BGMAX 4
#define KMAX 8192

__device__ int   g_ctr[BGMAX];                   // work counter (self-reset)
__device__ int   g_done[BGMAX];                  // CTA done counter (self-reset)
__device__ int   g_arr[BGMAX * KMAX];            // per-k arrivals (self-reset)
__device__ float g_scr[(size_t)BGMAX * KMAX * NQ * 64];

__device__ __forceinline__ int atom_add_acq_rel(int* ptr, int v) {
    int old;
    asm volatile("atom.global.add.acq_rel.gpu.s32 %0, [%1], %2;"
                 : "=r"(old) : "l"(ptr), "r"(v) : "memory");
    return old;
}

// One carry-window step: load NB new values, compute NB outputs, shift window.
template<int KLEN, int NB>
__device__ __forceinline__ const float* step(
    float* __restrict__ Y,           // window [KLEN-1+8]
    const float* __restrict__ p, int dp,
    const float* __restrict__ w, float bs,
    float& mx, int& ic)
{
#pragma unroll
    for (int t = 0; t < NB; t++) Y[KLEN - 1 + t] = p[t * dp];
#pragma unroll
    for (int i = 0; i < NB; i++) {
        float a = bs;
#pragma unroll
        for (int j = 0; j < KLEN; j++) a = fmaf(w[j], Y[i + j], a);
        mx = fmaxf(mx, a);              // FMNMX: alu pipe
        ic += (a > 0.0f) ? 1 : 0;       // FSETP + pred IADD
    }
#pragma unroll
    for (int t = 0; t < KLEN - 1; t++) Y[t] = Y[NB + t];
    return p + NB * dp;
}

template<int KLEN>
__device__ __forceinline__ void conv_range(
    const float* __restrict__ xsl,   // xs + lane
    int r, int pd, int mlo, int mhi, int d, int dp,
    const float* __restrict__ w, float bs,
    float& mx, int& ic)
{
    int n = mhi - mlo;
    if (n <= 0) return;
    const float* p = xsl + (HALO + r - pd + mlo * d) * XPITCH;
    float Y[KLEN - 1 + 8];
#pragma unroll
    for (int t = 0; t < KLEN - 1; t++) Y[t] = p[t * dp];    // prologue window
    p += (KLEN - 1) * dp;
    while (n >= 8) { p = step<KLEN, 8>(Y, p, dp, w, bs, mx, ic); n -= 8; }
    if (n & 4) p = step<KLEN, 4>(Y, p, dp, w, bs, mx, ic);
    if (n & 2) p = step<KLEN, 2>(Y, p, dp, w, bs, mx, ic);
    if (n & 1)     step<KLEN, 1>(Y, p, dp, w, bs, mx, ic);
}

template<int KLEN>
__device__ __forceinline__ void process_unit(
    const float* __restrict__ xsl, int d, int pd, int ol, int q,
    const float* __restrict__ w, float bs, float& mx, int& ic)
{
    const int dp = d * XPITCH;
    const int q0 = (ol - 1) / d;                 // one division per unit
    const int rr = (ol - 1) - q0 * d;
    if (d >= 4) {
        // Residue split: r = q, q+8, ... (units with q >= d are empty: fast skip)
        for (int r = q; r < d; r += NQ) {
            const int M = (r <= rr) ? q0 + 1 : q0;   // = ceil((ol-r)/d)
            conv_range<KLEN>(xsl, r, pd, 0, M, d, dp, w, bs, mx, ic);
        }
    } else {
        // m-subrange split by eighths (d in {1,2,3})
        for (int r = 0; r < d; r++) {
            const int M = (r <= rr) ? q0 + 1 : q0;
            conv_range<KLEN>(xsl, r, pd, (q * M) >> NQ_SHIFT,
                             ((q + 1) * M) >> NQ_SHIFT, d, dp, w, bs, mx, ic);
        }
    }
}

// Cold safe fallback for parameters outside the halo guarantee (not expected).
template<int KLEN>
__device__ __forceinline__ void process_unit_safe(
    const float* __restrict__ xsl, int d, int pd, int ol, int q, int T,
    const float* __restrict__ w, float bs, float& mx, int& ic)
{
    const int lo = (q * ol) >> NQ_SHIFT, hi = ((q + 1) * ol) >> NQ_SHIFT;
    for (int p = lo; p < hi; p++) {
        float a = bs;
#pragma unroll
        for (int j = 0; j < KLEN; j++) {
            const long long ix = (long long)p - pd + (long long)j * d;
            const int ixc = (int)min(max(ix, 0LL), (long long)(T - 1));
            float v = xsl[(HALO + ixc) * XPITCH];
            a = fmaf(w[j], (ix >= 0 && ix < T) ? v : 0.0f, a);
        }
        mx = fmaxf(mx, a);
        ic += (a > 0.0f) ? 1 : 0;
    }
}

__global__ void __launch_bounds__(32 * WARPS_PER_CTA, 2)
rf_main(const float* __restrict__ x,
        const float* __restrict__ w,
        const float* __restrict__ bias,
        const int*   __restrict__ dil,
        const int*   __restrict__ padr,
        const int*   __restrict__ olen,
        float* __restrict__ out,
        int B, int T, int K)
{
    extern __shared__ float xs[];                 // [(HALO+T+HALO)][XPITCH]
    const int lane = threadIdx.x & 31;
    const int warp = threadIdx.x >> 5;
    const int bg   = blockIdx.y;
    const int b0   = bg * 32;
    const int nb   = min(32, B - b0);

    // Transposed fill with zero halos: coalesced LDG, conflict-free STS (33 odd).
    for (int bb = warp; bb < 32; bb += WARPS_PER_CTA) {
        const int bsafe = min(bb, nb - 1);
        for (int t = lane; t < HALO; t += 32) {
            xs[t * XPITCH + bb] = 0.0f;
            xs[(HALO + T + t) * XPITCH + bb] = 0.0f;
        }
        for (int t = lane; t < T; t += 32) {
            float v = x[(size_t)(b0 + bsafe) * T + t];
            xs[(HALO + t) * XPITCH + bb] = (bb < nb) ? v : 0.0f;
        }
    }
    __syncthreads();

    const float* xsl = xs + lane;
    const int nunits = K * NQ;

    // Software-pipelined unit fetch: current u in flight while next is fetched.
    int u = 0;
    if (lane == 0) u = atomicAdd(&g_ctr[bg], 1);
    u = __shfl_sync(0xFFFFFFFFu, u, 0);

    while (u < nunits) {
        int unext = 0;
        if (lane == 0) unext = atomicAdd(&g_ctr[bg], 1);   // in flight during work

        const int k = u >> NQ_SHIFT;
        const int q = u & (NQ - 1);
        const int   d  = dil[k];
        const int   pd = padr[k];
        const int   ol = olen[k];
        const float bv = bias[k];

        float wreg[MAX_KLEN];
#pragma unroll
        for (int j = 0; j < MAX_KLEN; j++)
            wreg[j] = __ldg(&w[(size_t)k * MAX_KLEN + j]);

        float mx = -CUDART_INF_F;
        int   ic = 0;

        // klen inference: taps >= klen are exactly zero by construction.
        const int klen = (wreg[9] != 0.0f || wreg[10] != 0.0f) ? 11
                       : (wreg[7] != 0.0f || wreg[8] != 0.0f) ? 9 : 7;
        const bool safe = (d >= 1) && (pd < HALO) &&
                          ((ol - 1) - pd + (long long)(klen - 1) * d < T + HALO);

        if (safe) {
            if (klen == 11)      process_unit<11>(xsl, d, pd, ol, q, wreg, bv, mx, ic);
            else if (klen == 9)  process_unit<9>(xsl, d, pd, ol, q, wreg, bv, mx, ic);
            else                 process_unit<7>(xsl, d, pd, ol, q, wreg, bv, mx, ic);
        } else if (d >= 1) {
            if (klen == 11)      process_unit_safe<11>(xsl, d, pd, ol, q, T, wreg, bv, mx, ic);
            else if (klen == 9)  process_unit_safe<9>(xsl, d, pd, ol, q, T, wreg, bv, mx, ic);
            else                 process_unit_safe<7>(xsl, d, pd, ol, q, T, wreg, bv, mx, ic);
        }

        // Publish partial via L2 (no L1 copies -> no stale reads, no fences).
        float* s = g_scr + (((size_t)bg * KMAX + k) * NQ + q) * 64;
        __stcg(&s[lane], mx);
        __stcg(&s[32 + lane], (float)ic);
        // acq_rel arrival: releases our stores, acquires others' on the winner.
        int arrived = 0;
        if (lane == 0) arrived = atom_add_acq_rel(&g_arr[bg * KMAX + k], 1);
        arrived = __shfl_sync(0xFFFFFFFFu, arrived, 0);
        if (arrived == NQ - 1) {
            const float* sb = g_scr + (((size_t)bg * KMAX + k) * NQ) * 64;
            float M = __ldcg(&sb[lane]), C = __ldcg(&sb[32 + lane]);
#pragma unroll
            for (int q2 = 1; q2 < NQ; q2++) {
                M  = fmaxf(M, __ldcg(&sb[q2 * 64 + lane]));
                C += __ldcg(&sb[q2 * 64 + 32 + lane]);
            }
            if (lane < nb) {
                float* o = out + (size_t)(b0 + lane) * 2 * K + 2 * k;
                o[0] = M;
                o[1] = C / (float)ol;
            }
            if (lane == 0) g_arr[bg * KMAX + k] = 0;   // self-reset for replay
        }

        u = __shfl_sync(0xFFFFFFFFu, unext, 0);
    }

    // Last CTA per batch group resets the work counter for the next replay.
    __syncthreads();
    if (threadIdx.x == 0) {
        int dn = atomicAdd(&g_done[bg], 1);
        if (dn == (int)gridDim.x - 1) {
            g_ctr[bg]  = 0;
            g_done[bg] = 0;
        }
    }
}

extern "C" void kernel_launch(void* const* d_in, const int* in_sizes, int n_in,
                              void* d_out, int out_size) {
    const float* x    = (const float*)d_in[0];
    const float* w    = (const float*)d_in[1];
    const float* bias = (const float*)d_in[2];
    const int*   dil  = (const int*)d_in[3];
    const int*   padr = (const int*)d_in[4];
    const int*   olen = (const int*)d_in[5];
    float* out = (float*)d_out;

    const int K = in_sizes[2];                 // bias element count
    const int B = out_size / (2 * K);
    const int T = in_sizes[0] / B;
    const int nbg = (B + 31) / 32;             // batch groups (<= BGMAX)

    const size_t smem = (size_t)(2 * HALO + T) * XPITCH * sizeof(float);
    cudaFuncSetAttribute(rf_main,
                         cudaFuncAttributeMaxDynamicSharedMemorySize,
                         (int)smem);

    // 2 CTAs/SM x 148 SMs persistent, split across batch groups.
    int ctas_per_bg = (296 + nbg - 1) / nbg;
    dim3 grid(ctas_per_bg, nbg);
    rf_main<<<grid, 32 * WARPS_PER_CTA, smem>>>(x, w, bias, dil, padr, olen,
                                                out, B, T, K);
}